// round 1
// baseline (speedup 1.0000x reference)
#include <cuda_runtime.h>

// ---------------------------------------------------------------------------
// IntraSentenceAttention: out[b,i,:] = m_i * (sum_j e_ij x[b,j,:]) / (sum_j e_ij + eps)
//   e_ij = exp( dot(x_i, x_j) + min(i-j, 10) ) * m_j
// B=32, T=1024, D=128, fp32.
// Flash-style: i-tile (64 rows) per block, stream j-tiles (64), never
// materialize the 1024x1024 score matrix in HBM.
// ---------------------------------------------------------------------------

namespace {
constexpr int Bb = 32;
constexpr int Tt = 1024;
constexpr int Dd = 128;
constexpr int TM = 64;          // i-rows per block
constexpr int TN = 64;          // j-cols per tile
constexpr int XP = 132;         // SMEM pitch for X tiles (floats); 132 => 4-row stride = 16 mod 32,
                                // 1-row stride = 4 mod 32 (conflict-free with c = tx + 16n mapping)
constexpr int PP = 68;          // SMEM pitch for P tile (floats), 16B-aligned rows
constexpr float EPSF = 1e-7f;
constexpr int SMEM_FLOATS = TM * XP + TN * XP + TM * PP + TM /*rowsum*/ + TN /*mj*/ + TM /*mi*/;
constexpr int SMEM_BYTES = SMEM_FLOATS * 4;
}

// 0 = 1-byte bool, 1 = int32, 2 = float32
__device__ int g_mask_mode;

__global__ void detect_mask_kernel(const unsigned int* __restrict__ w, int nwords) {
    __shared__ int f01[2];
    if (threadIdx.x < 2) f01[threadIdx.x] = 0;
    __syncthreads();
    int not_int = 0, not_flt = 0;
    for (int i = threadIdx.x; i < nwords; i += blockDim.x) {
        unsigned v = w[i];
        if (v > 1u) not_int = 1;
        if (v != 0u && v != 0x3F800000u) not_flt = 1;
    }
    if (not_int) atomicOr(&f01[0], 1);
    if (not_flt) atomicOr(&f01[1], 1);
    __syncthreads();
    if (threadIdx.x == 0)
        g_mask_mode = (!f01[0]) ? 1 : ((!f01[1]) ? 2 : 0);
}

__device__ __forceinline__ float get_mask(const void* m, int idx, int mode) {
    if (mode == 1) return ((const int*)m)[idx] ? 1.0f : 0.0f;
    if (mode == 2) return ((const float*)m)[idx];
    return ((const unsigned char*)m)[idx] ? 1.0f : 0.0f;
}

__global__ __launch_bounds__(256, 2)
void attn_kernel(const float* __restrict__ x, const void* __restrict__ mask,
                 float* __restrict__ out) {
    extern __shared__ float smem[];
    float* sXi  = smem;                    // [TM][XP]
    float* sXj  = sXi + TM * XP;           // [TN][XP]
    float* sP   = sXj + TN * XP;           // [TM][PP]
    float* sRow = sP + TM * PP;            // [TM] running denominators
    float* sMj  = sRow + TM;               // [TN]
    float* sMi  = sMj + TN;                // [TM]

    const int b   = blockIdx.y;
    const int i0  = blockIdx.x * TM;
    const int tid = threadIdx.x;
    const int mode = g_mask_mode;

    const float* xb = x + (size_t)b * Tt * Dd;

    // --- load persistent Xi tile (coalesced) + row masks + init rowsums ---
    for (int e = tid; e < TM * (Dd / 4); e += 256) {
        int r  = e >> 5;               // Dd/4 = 32 float4 per row
        int c4 = (e & 31) << 2;
        *(float4*)(sXi + r * XP + c4) = *(const float4*)(xb + (size_t)(i0 + r) * Dd + c4);
    }
    if (tid < TM) {
        sMi[tid]  = get_mask(mask, b * Tt + i0 + tid, mode);
        sRow[tid] = 0.0f;
    }
    __syncthreads();

    // Phase-A mapping: 16x16 thread grid, 4x4 outputs; cols c = a_tx + 16*n
    const int a_tx = tid & 15;
    const int a_ty = tid >> 4;
    // Phase-B mapping: 16x16 grid; rows m = b_ty*4+mm; cols n0=b_tx*4 and 64+b_tx*4
    const int b_tx = tid & 15;
    const int b_ty = tid >> 4;

    float acc[4][8];
    #pragma unroll
    for (int m = 0; m < 4; m++)
        #pragma unroll
        for (int n = 0; n < 8; n++) acc[m][n] = 0.0f;

    for (int j0 = 0; j0 < Tt; j0 += TN) {
        // --- load Xj tile + column masks ---
        for (int e = tid; e < TN * (Dd / 4); e += 256) {
            int r  = e >> 5;
            int c4 = (e & 31) << 2;
            *(float4*)(sXj + r * XP + c4) = *(const float4*)(xb + (size_t)(j0 + r) * Dd + c4);
        }
        if (tid < TN) sMj[tid] = get_mask(mask, b * Tt + j0 + tid, mode);
        __syncthreads();

        // --- Phase A: S(4x4) = Xi_rows . Xj_rows, K = 128 ---
        float s[4][4];
        #pragma unroll
        for (int m = 0; m < 4; m++)
            #pragma unroll
            for (int n = 0; n < 4; n++) s[m][n] = 0.0f;

        {
            const float* pXi = sXi + (a_ty * 4) * XP;
            const float* pXj = sXj + a_tx * XP;
            #pragma unroll 2
            for (int k = 0; k < Dd; k += 4) {
                float4 xa[4], xv[4];
                #pragma unroll
                for (int m = 0; m < 4; m++) xa[m] = *(const float4*)(pXi + m * XP + k);
                #pragma unroll
                for (int n = 0; n < 4; n++) xv[n] = *(const float4*)(pXj + (n * 16) * XP + k);
                #pragma unroll
                for (int m = 0; m < 4; m++)
                    #pragma unroll
                    for (int n = 0; n < 4; n++)
                        s[m][n] += xa[m].x * xv[n].x + xa[m].y * xv[n].y +
                                   xa[m].z * xv[n].z + xa[m].w * xv[n].w;
            }
        }

        // --- exp + distance + column mask -> P ---
        #pragma unroll
        for (int m = 0; m < 4; m++) {
            const int i = i0 + a_ty * 4 + m;
            #pragma unroll
            for (int n = 0; n < 4; n++) {
                const int j = j0 + a_tx + 16 * n;
                float dterm = fminf((float)(i - j), 10.0f);
                float p = __expf(s[m][n] + dterm) * sMj[a_tx + 16 * n];
                sP[(a_ty * 4 + m) * PP + (a_tx + 16 * n)] = p;
            }
        }
        __syncthreads();

        // --- deterministic row-sum of P (denominator accumulation) ---
        {
            const int r = tid >> 2, seg = tid & 3;       // 4 lanes per row, contiguous in warp
            const float* pr = sP + r * PP + seg * 16;
            float part = 0.0f;
            #pragma unroll
            for (int c = 0; c < 16; c += 4) {
                float4 v = *(const float4*)(pr + c);
                part += v.x + v.y + v.z + v.w;
            }
            part += __shfl_down_sync(0xffffffffu, part, 2);
            part += __shfl_down_sync(0xffffffffu, part, 1);
            if (seg == 0) sRow[r] += part;               // one writer per row: deterministic
        }

        // --- Phase B: acc(4x8) += P(4xK) * Xj(KxD), K = 64 ---
        {
            const float* pP = sP + (b_ty * 4) * PP;
            const int n0 = b_tx * 4;
            #pragma unroll 2
            for (int k = 0; k < TN; k += 4) {
                float4 pv[4];
                #pragma unroll
                for (int m = 0; m < 4; m++) pv[m] = *(const float4*)(pP + m * PP + k);
                #pragma unroll
                for (int kk = 0; kk < 4; kk++) {
                    float4 v0 = *(const float4*)(sXj + (k + kk) * XP + n0);
                    float4 v1 = *(const float4*)(sXj + (k + kk) * XP + 64 + n0);
                    #pragma unroll
                    for (int m = 0; m < 4; m++) {
                        const float pm = ((const float*)&pv[m])[kk];
                        acc[m][0] += pm * v0.x; acc[m][1] += pm * v0.y;
                        acc[m][2] += pm * v0.z; acc[m][3] += pm * v0.w;
                        acc[m][4] += pm * v1.x; acc[m][5] += pm * v1.y;
                        acc[m][6] += pm * v1.z; acc[m][7] += pm * v1.w;
                    }
                }
            }
        }
        __syncthreads();   // protect sXj / sP / sRow before next tile
    }

    // --- epilogue: normalize, apply row mask, store ---
    #pragma unroll
    for (int m = 0; m < 4; m++) {
        const int r = b_ty * 4 + m;
        const float inv = sMi[r] / (sRow[r] + EPSF);
        float4 o0, o1;
        o0.x = acc[m][0] * inv; o0.y = acc[m][1] * inv;
        o0.z = acc[m][2] * inv; o0.w = acc[m][3] * inv;
        o1.x = acc[m][4] * inv; o1.y = acc[m][5] * inv;
        o1.z = acc[m][6] * inv; o1.w = acc[m][7] * inv;
        float* op = out + ((size_t)b * Tt + i0 + r) * Dd;
        *(float4*)(op + b_tx * 4)      = o0;
        *(float4*)(op + 64 + b_tx * 4) = o1;
    }
}

extern "C" void kernel_launch(void* const* d_in, const int* in_sizes, int n_in,
                              void* d_out, int out_size) {
    const float* x   = (const float*)d_in[0];
    const void* mask = d_in[1];
    float* out       = (float*)d_out;

    cudaFuncSetAttribute(attn_kernel, cudaFuncAttributeMaxDynamicSharedMemorySize, SMEM_BYTES);

    // Determine mask dtype (bool bytes / int32 / float32) deterministically on-device.
    // Reading (B*T)/4 words = 32 KB is in-bounds for every candidate dtype.
    detect_mask_kernel<<<1, 256>>>((const unsigned int*)mask, (Bb * Tt) / 4);

    dim3 grid(Tt / TM, Bb);
    attn_kernel<<<grid, 256, SMEM_BYTES>>>(x, mask, out);
}

// round 3
// speedup vs baseline: 3.3660x; 3.3660x over previous
#include <cuda_runtime.h>
#include <cstdint>

// ============================================================================
// IntraSentenceAttention, flash-style, both GEMMs on mma.sync tf32 (HMMA path;
// tcgen05 is unavailable: harness PTX target is sm_103 without the 'a' suffix).
//   S = Xi·Xjᵀ   (m16n8k8 tf32, k = d)
//   P = exp(S + min(i-j,10)) · mj      (register epilogue, P -> SMEM as tf32)
//   O += P·Xj    (m16n8k8 tf32, k = j)
// B=32, T=1024, D=128.  CTA: 128 i-rows, 16 j-tiles of 64.  256 thr / 8 warps.
// ============================================================================

namespace {
constexpr int Bb = 32, Tt = 1024, Dd = 128;
constexpr int TM = 128, TN = 64;
constexpr int NJT = Tt / TN;            // 16
constexpr float EPSF = 1e-7f;

constexpr int XIP = 132;                // sXi pitch (floats): bank = 4*row+qk, conflict-free
constexpr int XJP = 132;                // sXj pitch
constexpr int PPITCH = 68;              // sP pitch

// SMEM float offsets
constexpr int O_XI  = 0;                         // 128*132
constexpr int O_XJ  = O_XI + TM * XIP;           // 64*132
constexpr int O_P   = O_XJ + TN * XJP;           // 128*68
constexpr int O_MI  = O_P + TM * PPITCH;         // 128
constexpr int O_MJ  = O_MI + TM;                 // 64
constexpr int O_RP  = O_MJ + TN;                 // 2*128 row partials
constexpr int O_INV = O_RP + 2 * TM;             // 128
constexpr int SMEM_FLOATS = O_INV + TM;
constexpr int SMEM_BYTES = SMEM_FLOATS * 4;      // ~139 KB
}

__device__ int g_mask_mode;  // 0 = bool bytes, 1 = int32, 2 = float32

__global__ void detect_mask_kernel(const unsigned int* __restrict__ w, int nwords) {
    __shared__ int f01[2];
    if (threadIdx.x < 2) f01[threadIdx.x] = 0;
    __syncthreads();
    int not_int = 0, not_flt = 0;
    for (int i = threadIdx.x; i < nwords; i += blockDim.x) {
        unsigned v = w[i];
        if (v > 1u) not_int = 1;
        if (v != 0u && v != 0x3F800000u) not_flt = 1;
    }
    if (not_int) atomicOr(&f01[0], 1);
    if (not_flt) atomicOr(&f01[1], 1);
    __syncthreads();
    if (threadIdx.x == 0) g_mask_mode = (!f01[0]) ? 1 : ((!f01[1]) ? 2 : 0);
}

__device__ __forceinline__ float get_mask(const void* m, int idx, int mode) {
    if (mode == 1) return ((const int*)m)[idx] ? 1.0f : 0.0f;
    if (mode == 2) return ((const float*)m)[idx];
    return ((const unsigned char*)m)[idx] ? 1.0f : 0.0f;
}

__device__ __forceinline__ uint32_t rna_tf32_bits(float x) {
    uint32_t u;
    asm("cvt.rna.tf32.f32 %0, %1;" : "=r"(u) : "f"(x));
    return u;
}
__device__ __forceinline__ float rna_tf32(float x) { return __uint_as_float(rna_tf32_bits(x)); }

__device__ __forceinline__ void mma_tf32(float d[4], uint32_t a0, uint32_t a1,
                                         uint32_t a2, uint32_t a3,
                                         uint32_t b0, uint32_t b1) {
    asm volatile(
        "mma.sync.aligned.m16n8k8.row.col.f32.tf32.tf32.f32 "
        "{%0,%1,%2,%3}, {%4,%5,%6,%7}, {%8,%9}, {%0,%1,%2,%3};"
        : "+f"(d[0]), "+f"(d[1]), "+f"(d[2]), "+f"(d[3])
        : "r"(a0), "r"(a1), "r"(a2), "r"(a3), "r"(b0), "r"(b1));
}

__global__ __launch_bounds__(256, 1)
void attn_mma(const float* __restrict__ x, const void* __restrict__ mask,
              float* __restrict__ out) {
    extern __shared__ float smem[];
    float* sXi  = smem + O_XI;
    float* sXj  = smem + O_XJ;
    float* sP   = smem + O_P;
    float* sMi  = smem + O_MI;
    float* sMj  = smem + O_MJ;
    float* sRP  = smem + O_RP;
    float* sInv = smem + O_INV;
    const uint32_t* uXi = (const uint32_t*)sXi;
    const uint32_t* uXj = (const uint32_t*)sXj;
    const uint32_t* uP  = (const uint32_t*)sP;

    const int tid  = threadIdx.x;
    const int w    = tid >> 5, lane = tid & 31;
    const int band = w >> 1;          // 0..3 : 32-row m-band
    const int half = w & 1;           // phase A: j-half (32); phase B: d-half (64)
    const int qrow = lane >> 2;       // 0..7
    const int qk   = lane & 3;        // 0..3

    const int b  = blockIdx.y;
    const int i0 = blockIdx.x * TM;
    const int mode = g_mask_mode;
    const float* xb = x + (size_t)b * Tt * Dd;

    // ---- stage persistent Xi tile (rna-rounded), masks ----
    for (int e = tid; e < TM * 32; e += 256) {
        int r = e >> 5, f4 = (e & 31) << 2;
        float4 v = *(const float4*)(xb + (size_t)(i0 + r) * Dd + f4);
        v.x = rna_tf32(v.x); v.y = rna_tf32(v.y);
        v.z = rna_tf32(v.z); v.w = rna_tf32(v.w);
        *(float4*)(sXi + r * XIP + f4) = v;
    }
    if (tid < TM) sMi[tid] = get_mask(mask, b * Tt + i0 + tid, mode);
    __syncthreads();

    float acc[2][8][4];                        // O accum: [mfrag][nfrag][c]
    #pragma unroll
    for (int mf = 0; mf < 2; mf++)
        #pragma unroll
        for (int nf = 0; nf < 8; nf++)
            #pragma unroll
            for (int c = 0; c < 4; c++) acc[mf][nf][c] = 0.0f;

    float rsum[2][2] = {{0.f, 0.f}, {0.f, 0.f}};   // [mfrag][rowhalf]

    const int arow0 = band * 32;               // this warp's m-band base (local)

    for (int jt = 0; jt < NJT; ++jt) {
        const int j0 = jt * TN;

        // ---- stage Xj tile (rna-rounded) + column masks ----
        for (int e = tid; e < TN * 32; e += 256) {
            int r = e >> 5, f4 = (e & 31) << 2;
            float4 v = *(const float4*)(xb + (size_t)(j0 + r) * Dd + f4);
            v.x = rna_tf32(v.x); v.y = rna_tf32(v.y);
            v.z = rna_tf32(v.z); v.w = rna_tf32(v.w);
            *(float4*)(sXj + r * XJP + f4) = v;
        }
        if (tid < TN) sMj[tid] = get_mask(mask, b * Tt + j0 + tid, mode);
        __syncthreads();

        // ================= phase A: S(32x32 per warp) = Xi · Xjᵀ =================
        float s[2][4][4];
        #pragma unroll
        for (int mf = 0; mf < 2; mf++)
            #pragma unroll
            for (int nf = 0; nf < 4; nf++)
                #pragma unroll
                for (int c = 0; c < 4; c++) s[mf][nf][c] = 0.0f;

        #pragma unroll
        for (int ks = 0; ks < Dd / 8; ++ks) {
            const int k0 = ks * 8;
            uint32_t a[2][4];
            #pragma unroll
            for (int mf = 0; mf < 2; mf++) {
                const uint32_t* p = uXi + (arow0 + mf * 16 + qrow) * XIP + k0 + qk;
                a[mf][0] = p[0];
                a[mf][1] = p[8 * XIP];
                a[mf][2] = p[4];
                a[mf][3] = p[8 * XIP + 4];
            }
            #pragma unroll
            for (int nf = 0; nf < 4; nf++) {
                const uint32_t* p = uXj + (half * 32 + nf * 8 + qrow) * XJP + k0 + qk;
                uint32_t b0 = p[0], b1 = p[4];
                mma_tf32(s[0][nf], a[0][0], a[0][1], a[0][2], a[0][3], b0, b1);
                mma_tf32(s[1][nf], a[1][0], a[1][1], a[1][2], a[1][3], b0, b1);
            }
        }

        // ---- epilogue: P = exp(S + dist) * mj, rowsum, store P (tf32) ----
        #pragma unroll
        for (int mf = 0; mf < 2; mf++) {
            const int rl0 = arow0 + mf * 16 + qrow;       // local rows rl0, rl0+8
            const int ig0 = i0 + rl0;
            #pragma unroll
            for (int nf = 0; nf < 4; nf++) {
                const int jl = half * 32 + nf * 8 + 2 * qk;
                const int jg = j0 + jl;
                const float mj0 = sMj[jl], mj1 = sMj[jl + 1];
                float p0 = __expf(s[mf][nf][0] + fminf((float)(ig0 - jg), 10.f)) * mj0;
                float p1 = __expf(s[mf][nf][1] + fminf((float)(ig0 - jg - 1), 10.f)) * mj1;
                float p2 = __expf(s[mf][nf][2] + fminf((float)(ig0 + 8 - jg), 10.f)) * mj0;
                float p3 = __expf(s[mf][nf][3] + fminf((float)(ig0 + 8 - jg - 1), 10.f)) * mj1;
                rsum[mf][0] += p0 + p1;
                rsum[mf][1] += p2 + p3;
                uint2 u01 = make_uint2(rna_tf32_bits(p0), rna_tf32_bits(p1));
                uint2 u23 = make_uint2(rna_tf32_bits(p2), rna_tf32_bits(p3));
                *(uint2*)(sP + rl0 * PPITCH + jl)       = u01;
                *(uint2*)(sP + (rl0 + 8) * PPITCH + jl) = u23;
            }
        }
        __syncthreads();

        // ================= phase B: O(32x64 per warp) += P · Xj =================
        #pragma unroll
        for (int ks = 0; ks < TN / 8; ++ks) {
            const int k0 = ks * 8;
            uint32_t a[2][4];
            #pragma unroll
            for (int mf = 0; mf < 2; mf++) {
                const uint32_t* p = uP + (arow0 + mf * 16 + qrow) * PPITCH + k0 + qk;
                a[mf][0] = p[0];
                a[mf][1] = p[8 * PPITCH];
                a[mf][2] = p[4];
                a[mf][3] = p[8 * PPITCH + 4];
            }
            #pragma unroll
            for (int nf = 0; nf < 8; nf++) {
                // B[k=j][n=d] from row-major Xj  (2-way bank conflict accepted)
                const uint32_t* p = uXj + (k0 + qk) * XJP + half * 64 + nf * 8 + qrow;
                uint32_t b0 = p[0], b1 = p[4 * XJP];
                mma_tf32(acc[0][nf], a[0][0], a[0][1], a[0][2], a[0][3], b0, b1);
                mma_tf32(acc[1][nf], a[1][0], a[1][1], a[1][2], a[1][3], b0, b1);
            }
        }
        __syncthreads();   // protect sXj/sP before next tile
    }

    // ---- row-sum reduction: 4 lanes per row, then across the two j-halves ----
    #pragma unroll
    for (int mf = 0; mf < 2; mf++)
        #pragma unroll
        for (int rh = 0; rh < 2; rh++) {
            float v = rsum[mf][rh];
            v += __shfl_xor_sync(0xffffffffu, v, 1);
            v += __shfl_xor_sync(0xffffffffu, v, 2);
            if (qk == 0) sRP[half * TM + arow0 + mf * 16 + rh * 8 + qrow] = v;
        }
    __syncthreads();
    if (tid < TM) {
        float tot = sRP[tid] + sRP[TM + tid];
        sInv[tid] = sMi[tid] / (tot + EPSF);
    }
    __syncthreads();

    // ---- write O ----
    #pragma unroll
    for (int mf = 0; mf < 2; mf++) {
        const int rl0 = arow0 + mf * 16 + qrow;
        const float inv0 = sInv[rl0], inv1 = sInv[rl0 + 8];
        float* o0 = out + ((size_t)b * Tt + i0 + rl0) * Dd;
        float* o1 = o0 + 8 * Dd;
        #pragma unroll
        for (int nf = 0; nf < 8; nf++) {
            const int cl = half * 64 + nf * 8 + 2 * qk;
            *(float2*)(o0 + cl) = make_float2(acc[mf][nf][0] * inv0, acc[mf][nf][1] * inv0);
            *(float2*)(o1 + cl) = make_float2(acc[mf][nf][2] * inv1, acc[mf][nf][3] * inv1);
        }
    }
}

extern "C" void kernel_launch(void* const* d_in, const int* in_sizes, int n_in,
                              void* d_out, int out_size) {
    const float* x   = (const float*)d_in[0];
    const void* mask = d_in[1];
    float* out       = (float*)d_out;

    cudaFuncSetAttribute(attn_mma, cudaFuncAttributeMaxDynamicSharedMemorySize, SMEM_BYTES);

    detect_mask_kernel<<<1, 256>>>((const unsigned int*)mask, (Bb * Tt) / 4);
    dim3 grid(Tt / TM, Bb);
    attn_mma<<<grid, 256, SMEM_BYTES>>>(x, mask, out);
}